// round 2
// baseline (speedup 1.0000x reference)
#include <cuda_runtime.h>

#define BATCH 2048
#define TT    256
#define NVAL  32
#define HDIM  64
#define G3    192
#define LDIM  32
#define OHDIM 64
#define ODE_STEPS 192

// ---------------- persistent scratch (no allocations allowed) ----------------
__device__ float g_h[BATCH * HDIM];     // GRU final hidden
__device__ float g_z[BATCH * LDIM];     // latent state (z0, then z(48))
__device__ float g_klpart[256];         // per-block KL partial sums

// ---------------- fast transcendental helpers ----------------
__device__ __forceinline__ float fsig(float x) {
    x = fminf(fmaxf(x, -30.f), 30.f);
    return __fdividef(1.f, 1.f + __expf(-x));
}
__device__ __forceinline__ float ftanh(float x) {
    x = fminf(fmaxf(x, -15.f), 15.f);
    float e = __expf(2.f * x);
    return __fdividef(e - 1.f, e + 1.f);
}

// =====================================================================
// Kernel 1: fused input-projection + GRU scan.
// Each block owns 16 batch rows for the whole scan. Weights transposed in
// dynamic smem (conflict-free reads: consecutive j per lane).
// =====================================================================
__global__ __launch_bounds__(256) void gru_kernel(
    const float* __restrict__ values, const float* __restrict__ mask,
    const int* __restrict__ seqlen,
    const float* __restrict__ W_ih, const float* __restrict__ W_hh,
    const float* __restrict__ b_ih, const float* __restrict__ b_hh)
{
    extern __shared__ float sm[];
    float* Wi = sm;                    // [64][192]  Wi[k*192+g] = W_ih[g][k]
    float* Wh = Wi + HDIM * G3;        // [64][192]
    float* bi = Wh + HDIM * G3;        // [192]
    float* bh = bi + G3;               // [192]
    float* xs = bh + G3;               // [16][64]
    float* hs = xs + 16 * 64;          // [2][16][64] double buffered
    __shared__ int seq_s[16];

    const int tid = threadIdx.x;
    const int b0  = blockIdx.x * 16;

    for (int i = tid; i < G3 * HDIM; i += 256) {
        int g = i >> 6, k = i & 63;          // input row-major [g][k], coalesced read
        Wi[k * G3 + g] = W_ih[i];
        Wh[k * G3 + g] = W_hh[i];
    }
    for (int i = tid; i < G3; i += 256) { bi[i] = b_ih[i]; bh[i] = b_hh[i]; }
    for (int i = tid; i < 16 * 64; i += 256) { hs[i] = 0.f; hs[16 * 64 + i] = 0.f; }
    if (tid < 16) seq_s[tid] = seqlen[b0 + tid];
    __syncthreads();

    int tmax = 0;
    #pragma unroll
    for (int r = 0; r < 16; r++) tmax = max(tmax, seq_s[r]);

    const int j  = tid & 63;
    const int rg = tid >> 6;   // 4 row-groups of 4 rows

    for (int t = 0; t < tmax; t++) {
        const int tr = TT - 1 - t;   // reversed-sequence index
        // stage x = concat(values, mask) for the 16 rows at time tr
        for (int i = tid; i < 16 * 64; i += 256) {
            int r = i >> 6, k = i & 63;
            int base = ((b0 + r) * TT + tr) * NVAL;
            xs[i] = (k < NVAL) ? values[base + k] : mask[base + k - NVAL];
        }
        __syncthreads();

        const float* hcur = hs + (t & 1) * 1024;
        float*       hnxt = hs + ((t & 1) ^ 1) * 1024;

        float rp[4], zp[4], xn[4], hn[4];
        #pragma unroll
        for (int rr = 0; rr < 4; rr++) {
            rp[rr] = bi[j]       + bh[j];
            zp[rr] = bi[j + 64]  + bh[j + 64];
            xn[rr] = bi[j + 128];
            hn[rr] = bh[j + 128];
        }
        #pragma unroll 4
        for (int k = 0; k < 64; k++) {
            float w0 = Wi[k * G3 + j], w1 = Wi[k * G3 + j + 64], w2 = Wi[k * G3 + j + 128];
            float v0 = Wh[k * G3 + j], v1 = Wh[k * G3 + j + 64], v2 = Wh[k * G3 + j + 128];
            #pragma unroll
            for (int rr = 0; rr < 4; rr++) {
                int r = rg * 4 + rr;
                float xv = xs[r * 64 + k];
                float hv = hcur[r * 64 + k];
                rp[rr] += xv * w0 + hv * v0;
                zp[rr] += xv * w1 + hv * v1;
                xn[rr] += xv * w2;
                hn[rr] += hv * v2;
            }
        }
        #pragma unroll
        for (int rr = 0; rr < 4; rr++) {
            int r = rg * 4 + rr;
            float hold  = hcur[r * 64 + j];
            float rgate = fsig(rp[rr]);
            float zgate = fsig(zp[rr]);
            float n     = ftanh(xn[rr] + rgate * hn[rr]);
            float hnew  = (1.f - zgate) * n + zgate * hold;
            hnxt[r * 64 + j] = (t < seq_s[r]) ? hnew : hold;
        }
        __syncthreads();
    }

    const float* hf = hs + (tmax & 1) * 1024;
    for (int i = tid; i < 16 * 64; i += 256) {
        int r = i >> 6, k = i & 63;
        g_h[(b0 + r) * HDIM + k] = hf[i];
    }
}

// =====================================================================
// Kernel 2: z0 = mean + eps*exp(0.5*logvar); KL partial sums.
// One thread per (b, l).
// =====================================================================
__global__ __launch_bounds__(256) void z0_kernel(
    const float* __restrict__ eps, const float* __restrict__ W_z0,
    const float* __restrict__ b_z0)
{
    __shared__ float Wz[64 * 64];   // transposed: Wz[k*64+g] = W_z0[g][k]
    __shared__ float bz[64];
    __shared__ float red[256];
    int tid = threadIdx.x;
    for (int i = tid; i < 64 * 64; i += 256) {
        int g = i >> 6, k = i & 63;
        Wz[k * 64 + g] = W_z0[i];
    }
    if (tid < 64) bz[tid] = b_z0[tid];
    __syncthreads();

    int idx = blockIdx.x * 256 + tid;
    int b = idx >> 5, l = idx & 31;
    float m  = bz[l];
    float lv = bz[l + 32];
    const float* hb = g_h + b * 64;
    #pragma unroll 8
    for (int k = 0; k < 64; k++) {
        float hv = hb[k];                 // broadcast within warp
        m  += hv * Wz[k * 64 + l];
        lv += hv * Wz[k * 64 + l + 32];
    }
    g_z[idx] = m + eps[idx] * __expf(0.5f * lv);
    float klv = 1.f + lv - m * m - __expf(lv);

    red[tid] = klv;
    __syncthreads();
    for (int s = 128; s > 0; s >>= 1) {
        if (tid < s) red[tid] += red[tid + s];
        __syncthreads();
    }
    if (tid == 0) g_klpart[blockIdx.x] = red[0];
}

// =====================================================================
// Kernel 3: fixed-step RK4 integration of the latent ODE, t in [0,48].
// 16 rows/block, 128 blocks (one wave), weights in static smem.
// =====================================================================
__global__ __launch_bounds__(1024) void ode_kernel(
    const float* __restrict__ W1, const float* __restrict__ b1,
    const float* __restrict__ W2, const float* __restrict__ b2,
    const float* __restrict__ W3, const float* __restrict__ b3)
{
    __shared__ float W1t[32 * 64];   // W1t[k*64+j] = W1[j][k]   (j<64,k<32)
    __shared__ float W2t[64 * 64];   // W2t[k*64+j] = W2[j][k]
    __shared__ float W3t[64 * 32];   // W3t[k*32+j] = W3[j][k]   (j<32,k<64)
    __shared__ float sb1[64], sb2[64], sb3[32];
    __shared__ float zs[16 * 32];
    __shared__ float h1[16 * 64];    // f (16*32) aliases the front of h1
    __shared__ float h2[16 * 64];
    __shared__ float acc[16 * 32];
    __shared__ float zt[16 * 32];
    float* f = h1;                   // alias: h1 is dead when f is produced

    const int tid = threadIdx.x;
    const int r = tid >> 6, j = tid & 63;

    for (int i = tid; i < 64 * 32; i += 1024) { int jj = i >> 5, k = i & 31; W1t[k * 64 + jj] = W1[i]; }
    for (int i = tid; i < 64 * 64; i += 1024) { int jj = i >> 6, k = i & 63; W2t[k * 64 + jj] = W2[i]; }
    for (int i = tid; i < 32 * 64; i += 1024) { int jj = i >> 6, k = i & 63; W3t[k * 32 + jj] = W3[i]; }
    if (tid < 64) { sb1[tid] = b1[tid]; sb2[tid] = b2[tid]; }
    if (tid < 32) sb3[tid] = b3[tid];
    const int b0 = blockIdx.x * 16;
    for (int i = tid; i < 16 * 32; i += 1024) zs[i] = g_z[b0 * 32 + i];
    __syncthreads();

    const float hstep = 48.f / (float)ODE_STEPS;

    // one MLP eval: src[16][32] -> f[16][32]
    auto mlp_eval = [&](const float* src) {
        float s = sb1[j];
        #pragma unroll
        for (int k = 0; k < 32; k++) s += src[r * 32 + k] * W1t[k * 64 + j];
        h1[r * 64 + j] = ftanh(s);
        __syncthreads();
        s = sb2[j];
        #pragma unroll
        for (int k = 0; k < 64; k++) s += h1[r * 64 + k] * W2t[k * 64 + j];
        float h2v = ftanh(s);
        __syncthreads();             // all h1 reads done before f overwrites h1
        h2[r * 64 + j] = h2v;
        __syncthreads();
        if (j < 32) {
            float s3 = sb3[j];
            #pragma unroll
            for (int k = 0; k < 64; k++) s3 += h2[r * 64 + k] * W3t[k * 32 + j];
            f[r * 32 + j] = s3;
        }
        __syncthreads();
    };

    for (int s = 0; s < ODE_STEPS; s++) {
        mlp_eval(zs);                                        // k1
        if (tid < 512) { acc[tid] = f[tid]; zt[tid] = zs[tid] + 0.5f * hstep * f[tid]; }
        __syncthreads();
        mlp_eval(zt);                                        // k2
        if (tid < 512) { acc[tid] += 2.f * f[tid]; zt[tid] = zs[tid] + 0.5f * hstep * f[tid]; }
        __syncthreads();
        mlp_eval(zt);                                        // k3
        if (tid < 512) { acc[tid] += 2.f * f[tid]; zt[tid] = zs[tid] + hstep * f[tid]; }
        __syncthreads();
        mlp_eval(zt);                                        // k4
        if (tid < 512) { zs[tid] += (hstep / 6.f) * (acc[tid] + f[tid]); }
        __syncthreads();
    }

    for (int i = tid; i < 16 * 32; i += 1024) g_z[b0 * 32 + i] = zs[i];
}

// =====================================================================
// Kernel 4: decoder MLP -> logits; block 8 reduces KL.
// =====================================================================
__global__ __launch_bounds__(256) void dec_kernel(
    const float* __restrict__ dW1, const float* __restrict__ db1,
    const float* __restrict__ dW2, const float* __restrict__ db2,
    float* __restrict__ out, int out_size)
{
    int tid = threadIdx.x;
    if (blockIdx.x < 8) {
        __shared__ float W1s[64 * 32];
        __shared__ float b1s[64];
        __shared__ float W2s[64];
        for (int i = tid; i < 64 * 32; i += 256) W1s[i] = dW1[i];
        if (tid < 64) { b1s[tid] = db1[tid]; W2s[tid] = dW2[tid]; }
        __syncthreads();
        int b = blockIdx.x * 256 + tid;
        float zr[32];
        #pragma unroll
        for (int k = 0; k < 32; k++) zr[k] = g_z[b * 32 + k];
        float accv = db2[0];
        #pragma unroll 2
        for (int jj = 0; jj < 64; jj++) {
            float s = b1s[jj];
            #pragma unroll
            for (int k = 0; k < 32; k++) s += zr[k] * W1s[jj * 32 + k];
            accv += fmaxf(s, 0.f) * W2s[jj];
        }
        out[b] = accv;
    } else {
        __shared__ float red[256];
        red[tid] = g_klpart[tid];
        __syncthreads();
        for (int s = 128; s > 0; s >>= 1) {
            if (tid < s) red[tid] += red[tid + s];
            __syncthreads();
        }
        if (tid == 0) out[out_size - 1] = -0.5f * red[0] / (float)(BATCH * LDIM);
    }
}

// =====================================================================
extern "C" void kernel_launch(void* const* d_in, const int* in_sizes, int n_in,
                              void* d_out, int out_size)
{
    // metadata order: times, values, mask, seq_lengths, eps, W_ih, W_hh,
    // b_ih, b_hh, W_z0, b_z0, ode_W1..ode_b3, dec_W1..dec_b2
    const float* values = (const float*)d_in[1];
    const float* mask   = (const float*)d_in[2];
    const int*   seqlen = (const int*)d_in[3];
    const float* eps    = (const float*)d_in[4];
    const float* W_ih   = (const float*)d_in[5];
    const float* W_hh   = (const float*)d_in[6];
    const float* b_ih   = (const float*)d_in[7];
    const float* b_hh   = (const float*)d_in[8];
    const float* W_z0   = (const float*)d_in[9];
    const float* b_z0   = (const float*)d_in[10];
    const float* oW1    = (const float*)d_in[11];
    const float* ob1    = (const float*)d_in[12];
    const float* oW2    = (const float*)d_in[13];
    const float* ob2    = (const float*)d_in[14];
    const float* oW3    = (const float*)d_in[15];
    const float* ob3    = (const float*)d_in[16];
    const float* dW1    = (const float*)d_in[17];
    const float* db1    = (const float*)d_in[18];
    const float* dW2    = (const float*)d_in[19];
    const float* db2    = (const float*)d_in[20];
    float* out = (float*)d_out;

    size_t smem = (size_t)(2 * HDIM * G3 + 2 * G3 + 16 * 64 + 2 * 16 * 64) * sizeof(float);
    cudaFuncSetAttribute((const void*)gru_kernel,
                         cudaFuncAttributeMaxDynamicSharedMemorySize, (int)smem);

    gru_kernel<<<BATCH / 16, 256, smem>>>(values, mask, seqlen, W_ih, W_hh, b_ih, b_hh);
    z0_kernel<<<(BATCH * LDIM) / 256, 256>>>(eps, W_z0, b_z0);
    ode_kernel<<<BATCH / 16, 1024>>>(oW1, ob1, oW2, ob2, oW3, ob3);
    dec_kernel<<<9, 256>>>(dW1, db1, dW2, db2, out, out_size);
}

// round 3
// speedup vs baseline: 2.9084x; 2.9084x over previous
#include <cuda_runtime.h>

#define BATCH 2048
#define TT    256
#define NVAL  32
#define HDIM  64
#define G3    192
#define LDIM  32
#define OHDIM 64
#define ODE_STEPS 48

typedef unsigned long long u64;

// ---------------- persistent scratch ----------------
__device__ float g_h[BATCH * HDIM];
__device__ float g_z[BATCH * LDIM];
__device__ float g_klpart[256];

// ---------------- f32x2 packed-FMA helpers (sm_100a) ----------------
__device__ __forceinline__ u64 ffma2(u64 a, u64 b, u64 c) {
    u64 d;
    asm("fma.rn.f32x2 %0, %1, %2, %3;" : "=l"(d) : "l"(a), "l"(b), "l"(c));
    return d;
}
__device__ __forceinline__ u64 fpack2(float lo, float hi) {
    u64 v;
    asm("mov.b64 %0, {%1, %2};" : "=l"(v) : "f"(lo), "f"(hi));
    return v;
}
__device__ __forceinline__ float fsum2(u64 v) {
    float lo, hi;
    asm("mov.b64 {%0, %1}, %2;" : "=f"(lo), "=f"(hi) : "l"(v));
    return lo + hi;
}

// ---------------- fast transcendentals ----------------
__device__ __forceinline__ float fsig(float x) {
    x = fminf(fmaxf(x, -30.f), 30.f);
    return __fdividef(1.f, 1.f + __expf(-x));
}
__device__ __forceinline__ float ftanh(float x) {
    x = fminf(fmaxf(x, -15.f), 15.f);
    float e = __expf(2.f * x);
    return __fdividef(e - 1.f, e + 1.f);
}

// =====================================================================
// Kernel 1: fused input-projection + GRU scan. 16 rows/block, 256 thr.
// k-major weights in smem (conflict-free); inner loop pairs k via f32x2.
// One __syncthreads per timestep; next-step x prefetched into registers.
// =====================================================================
__global__ __launch_bounds__(256) void gru_kernel(
    const float* __restrict__ values, const float* __restrict__ mask,
    const int* __restrict__ seqlen,
    const float* __restrict__ W_ih, const float* __restrict__ W_hh,
    const float* __restrict__ b_ih, const float* __restrict__ b_hh)
{
    extern __shared__ float sm[];
    float* Wi = sm;                    // [64][192]  Wi[k*192+g] = W_ih[g][k]
    float* Wh = Wi + HDIM * G3;        // [64][192]
    float* xs = Wh + HDIM * G3;        // [2][16][64]
    float* hs = xs + 2 * 1024;         // [2][16][64]
    float* bi = hs + 2 * 1024;         // [192]
    float* bh = bi + G3;               // [192]
    __shared__ int seq_s[16];

    const int tid = threadIdx.x;
    const int b0  = blockIdx.x * 16;

    for (int i = tid; i < G3 * HDIM; i += 256) {
        int g = i >> 6, k = i & 63;
        Wi[k * G3 + g] = W_ih[i];
        Wh[k * G3 + g] = W_hh[i];
    }
    for (int i = tid; i < G3; i += 256) { bi[i] = b_ih[i]; bh[i] = b_hh[i]; }
    for (int i = tid; i < 2 * 1024; i += 256) hs[i] = 0.f;
    if (tid < 16) seq_s[tid] = seqlen[b0 + tid];

    // stage x for t=0 (tr = TT-1)
    for (int i = tid; i < 1024; i += 256) {
        int r = i >> 6, k = i & 63;
        int base = ((b0 + r) * TT + (TT - 1)) * NVAL;
        xs[i] = (k < NVAL) ? values[base + k] : mask[base + k - NVAL];
    }
    __syncthreads();

    int tmax = 0;
    #pragma unroll
    for (int r = 0; r < 16; r++) tmax = max(tmax, seq_s[r]);

    const int j  = tid & 63;
    const int rg = tid >> 6;

    for (int t = 0; t < tmax; t++) {
        const int cur = t & 1;
        const float* xcur = xs + cur * 1024;
        const float* hcur = hs + cur * 1024;
        float*       hnxt = hs + (cur ^ 1) * 1024;
        float*       xnxt = xs + (cur ^ 1) * 1024;

        // prefetch next timestep's x into registers (overlaps compute)
        float pf[4];
        const bool do_pf = (t + 1 < tmax);
        if (do_pf) {
            const int tr2 = TT - 2 - t;
            #pragma unroll
            for (int q = 0; q < 4; q++) {
                int i = tid + q * 256;
                int r = i >> 6, k = i & 63;
                int base = ((b0 + r) * TT + tr2) * NVAL;
                pf[q] = (k < NVAL) ? values[base + k] : mask[base + k - NVAL];
            }
        }

        u64 aR[4], aZ[4], aN[4], aH[4];
        #pragma unroll
        for (int rr = 0; rr < 4; rr++) { aR[rr] = 0; aZ[rr] = 0; aN[rr] = 0; aH[rr] = 0; }

        #pragma unroll 4
        for (int kk = 0; kk < 32; kk++) {
            const int k = kk * 2;
            const float* wa = Wi + k * G3;
            const float* wb = Wi + (k + 1) * G3;
            const float* va = Wh + k * G3;
            const float* vb = Wh + (k + 1) * G3;
            u64 w0 = fpack2(wa[j],       wb[j]);
            u64 w1 = fpack2(wa[j + 64],  wb[j + 64]);
            u64 w2 = fpack2(wa[j + 128], wb[j + 128]);
            u64 v0 = fpack2(va[j],       vb[j]);
            u64 v1 = fpack2(va[j + 64],  vb[j + 64]);
            u64 v2 = fpack2(va[j + 128], vb[j + 128]);
            #pragma unroll
            for (int rr = 0; rr < 4; rr++) {
                const int r = rg * 4 + rr;
                u64 xv = *(const u64*)&xcur[r * 64 + k];   // LDS.64 broadcast
                u64 hv = *(const u64*)&hcur[r * 64 + k];
                aR[rr] = ffma2(xv, w0, ffma2(hv, v0, aR[rr]));
                aZ[rr] = ffma2(xv, w1, ffma2(hv, v1, aZ[rr]));
                aN[rr] = ffma2(xv, w2, aN[rr]);
                aH[rr] = ffma2(hv, v2, aH[rr]);
            }
        }

        const float biR = bi[j] + bh[j];
        const float biZ = bi[j + 64] + bh[j + 64];
        const float biN = bi[j + 128];
        const float bhN = bh[j + 128];
        #pragma unroll
        for (int rr = 0; rr < 4; rr++) {
            const int r = rg * 4 + rr;
            float hold  = hcur[r * 64 + j];
            float rgate = fsig(fsum2(aR[rr]) + biR);
            float zgate = fsig(fsum2(aZ[rr]) + biZ);
            float n     = ftanh(fsum2(aN[rr]) + biN + rgate * (fsum2(aH[rr]) + bhN));
            float hnew  = (1.f - zgate) * n + zgate * hold;
            hnxt[r * 64 + j] = (t < seq_s[r]) ? hnew : hold;
        }

        if (do_pf) {
            #pragma unroll
            for (int q = 0; q < 4; q++) xnxt[tid + q * 256] = pf[q];
        }
        __syncthreads();
    }

    const float* hf = hs + (tmax & 1) * 1024;
    for (int i = tid; i < 1024; i += 256) {
        int r = i >> 6, k = i & 63;
        g_h[(b0 + r) * HDIM + k] = hf[i];
    }
}

// =====================================================================
// Kernel 2: z0 sample + KL partials.
// =====================================================================
__global__ __launch_bounds__(256) void z0_kernel(
    const float* __restrict__ eps, const float* __restrict__ W_z0,
    const float* __restrict__ b_z0)
{
    __shared__ float Wz[64 * 64];
    __shared__ float bz[64];
    __shared__ float red[256];
    int tid = threadIdx.x;
    for (int i = tid; i < 64 * 64; i += 256) {
        int g = i >> 6, k = i & 63;
        Wz[k * 64 + g] = W_z0[i];
    }
    if (tid < 64) bz[tid] = b_z0[tid];
    __syncthreads();

    int idx = blockIdx.x * 256 + tid;
    int b = idx >> 5, l = idx & 31;
    float m  = bz[l];
    float lv = bz[l + 32];
    const float* hb = g_h + b * 64;
    #pragma unroll 8
    for (int k = 0; k < 64; k++) {
        float hv = hb[k];
        m  += hv * Wz[k * 64 + l];
        lv += hv * Wz[k * 64 + l + 32];
    }
    g_z[idx] = m + eps[idx] * __expf(0.5f * lv);
    float klv = 1.f + lv - m * m - __expf(lv);

    red[tid] = klv;
    __syncthreads();
    for (int s = 128; s > 0; s >>= 1) {
        if (tid < s) red[tid] += red[tid + s];
        __syncthreads();
    }
    if (tid == 0) g_klpart[blockIdx.x] = red[0];
}

// =====================================================================
// Kernel 3: RK4 latent-ODE + fused decoder epilogue.
// 256 threads, 16 rows/block; f32x2 over paired k.
// =====================================================================
__global__ __launch_bounds__(256) void ode_kernel(
    const float* __restrict__ W1, const float* __restrict__ b1,
    const float* __restrict__ W2, const float* __restrict__ b2,
    const float* __restrict__ W3, const float* __restrict__ b3,
    const float* __restrict__ dW1, const float* __restrict__ db1,
    const float* __restrict__ dW2, const float* __restrict__ db2,
    float* __restrict__ out)
{
    extern __shared__ float sm[];
    float* W1t = sm;            // [32][64]  W1t[k*64+j] = W1[j][k]
    float* W2t = W1t + 2048;    // [64][64]
    float* W3t = W2t + 4096;    // [64][32]
    float* zs  = W3t + 2048;    // [16][32]
    float* zt  = zs + 512;
    float* acc = zt + 512;
    float* fs  = acc + 512;
    float* h1  = fs + 512;      // [16][64]
    float* h2  = h1 + 1024;     // [16][64]
    float* sb1 = h2 + 1024;     // [64]
    float* sb2 = sb1 + 64;      // [64]
    float* sb3 = sb2 + 64;      // [32]

    const int tid = threadIdx.x;
    const int j  = tid & 63;
    const int rg = tid >> 6;
    const int b0 = blockIdx.x * 16;

    for (int i = tid; i < 64 * 32; i += 256) { int jj = i >> 5, k = i & 31; W1t[k * 64 + jj] = W1[i]; }
    for (int i = tid; i < 64 * 64; i += 256) { int jj = i >> 6, k = i & 63; W2t[k * 64 + jj] = W2[i]; }
    for (int i = tid; i < 32 * 64; i += 256) { int jj = i >> 6, k = i & 63; W3t[k * 32 + jj] = W3[i]; }
    if (tid < 64) { sb1[tid] = b1[tid]; sb2[tid] = b2[tid]; }
    if (tid < 32) sb3[tid] = b3[tid];
    for (int i = tid; i < 512; i += 256) zs[i] = g_z[b0 * 32 + i];
    __syncthreads();

    const float hstep = 48.f / (float)ODE_STEPS;

    auto mlp_eval = [&](const float* src) {
        // L1: src[16][32] -> h1[16][64]
        {
            u64 a[4] = {0, 0, 0, 0};
            #pragma unroll 4
            for (int kk = 0; kk < 16; kk++) {
                const int k = kk * 2;
                u64 w = fpack2(W1t[k * 64 + j], W1t[(k + 1) * 64 + j]);
                #pragma unroll
                for (int rr = 0; rr < 4; rr++) {
                    u64 s2 = *(const u64*)&src[(rg * 4 + rr) * 32 + k];
                    a[rr] = ffma2(s2, w, a[rr]);
                }
            }
            float bb = sb1[j];
            #pragma unroll
            for (int rr = 0; rr < 4; rr++)
                h1[(rg * 4 + rr) * 64 + j] = ftanh(fsum2(a[rr]) + bb);
        }
        __syncthreads();
        // L2: h1 -> h2
        {
            u64 a[4] = {0, 0, 0, 0};
            #pragma unroll 4
            for (int kk = 0; kk < 32; kk++) {
                const int k = kk * 2;
                u64 w = fpack2(W2t[k * 64 + j], W2t[(k + 1) * 64 + j]);
                #pragma unroll
                for (int rr = 0; rr < 4; rr++) {
                    u64 s2 = *(const u64*)&h1[(rg * 4 + rr) * 64 + k];
                    a[rr] = ffma2(s2, w, a[rr]);
                }
            }
            float bb = sb2[j];
            #pragma unroll
            for (int rr = 0; rr < 4; rr++)
                h2[(rg * 4 + rr) * 64 + j] = ftanh(fsum2(a[rr]) + bb);
        }
        __syncthreads();
        // L3: h2 -> fs[16][32] (half the lanes)
        if (j < 32) {
            u64 a[4] = {0, 0, 0, 0};
            #pragma unroll 4
            for (int kk = 0; kk < 32; kk++) {
                const int k = kk * 2;
                u64 w = fpack2(W3t[k * 32 + j], W3t[(k + 1) * 32 + j]);
                #pragma unroll
                for (int rr = 0; rr < 4; rr++) {
                    u64 s2 = *(const u64*)&h2[(rg * 4 + rr) * 64 + k];
                    a[rr] = ffma2(s2, w, a[rr]);
                }
            }
            float bb = sb3[j];
            #pragma unroll
            for (int rr = 0; rr < 4; rr++)
                fs[(rg * 4 + rr) * 32 + j] = fsum2(a[rr]) + bb;
        }
        __syncthreads();
    };

    const int i0 = 2 * tid;
    for (int s = 0; s < ODE_STEPS; s++) {
        mlp_eval(zs);
        #pragma unroll
        for (int q = 0; q < 2; q++) { int i = i0 + q; float fv = fs[i]; acc[i] = fv; zt[i] = zs[i] + 0.5f * hstep * fv; }
        __syncthreads();
        mlp_eval(zt);
        #pragma unroll
        for (int q = 0; q < 2; q++) { int i = i0 + q; float fv = fs[i]; acc[i] += 2.f * fv; zt[i] = zs[i] + 0.5f * hstep * fv; }
        __syncthreads();
        mlp_eval(zt);
        #pragma unroll
        for (int q = 0; q < 2; q++) { int i = i0 + q; float fv = fs[i]; acc[i] += 2.f * fv; zt[i] = zs[i] + hstep * fv; }
        __syncthreads();
        mlp_eval(zt);
        #pragma unroll
        for (int q = 0; q < 2; q++) { int i = i0 + q; zs[i] += (hstep / 6.f) * (acc[i] + fs[i]); }
        __syncthreads();
    }

    // ---------- fused decoder: logits for this block's 16 rows ----------
    // reuse h1 (dead) for dW1 [64][32]; acc for db1 / dW2.
    for (int i = tid; i < 64 * 32; i += 256) h1[i] = dW1[i];
    if (tid < 64) { acc[tid] = db1[tid]; acc[64 + tid] = dW2[tid]; }
    __syncthreads();

    const int lane = tid & 31;
    const int wrp  = tid >> 5;
    #pragma unroll
    for (int rr = 0; rr < 4; rr++) {
        const int r = rg * 4 + rr;
        float s = acc[j];
        #pragma unroll 8
        for (int k = 0; k < 32; k++) s += zs[r * 32 + k] * h1[j * 32 + k];
        float v = fmaxf(s, 0.f) * acc[64 + j];
        #pragma unroll
        for (int off = 16; off > 0; off >>= 1) v += __shfl_down_sync(0xffffffffu, v, off);
        if (lane == 0) fs[wrp * 4 + rr] = v;
    }
    __syncthreads();
    if (tid < 16) {
        int g = tid >> 2, rr = tid & 3;
        out[b0 + tid] = db2[0] + fs[(2 * g) * 4 + rr] + fs[(2 * g + 1) * 4 + rr];
    }
}

// =====================================================================
// Kernel 4: KL final reduce (1 block).
// =====================================================================
__global__ __launch_bounds__(256) void kl_kernel(float* __restrict__ out, int out_size)
{
    __shared__ float red[256];
    int tid = threadIdx.x;
    red[tid] = g_klpart[tid];
    __syncthreads();
    for (int s = 128; s > 0; s >>= 1) {
        if (tid < s) red[tid] += red[tid + s];
        __syncthreads();
    }
    if (tid == 0) out[out_size - 1] = -0.5f * red[0] / (float)(BATCH * LDIM);
}

// =====================================================================
extern "C" void kernel_launch(void* const* d_in, const int* in_sizes, int n_in,
                              void* d_out, int out_size)
{
    const float* values = (const float*)d_in[1];
    const float* mask   = (const float*)d_in[2];
    const int*   seqlen = (const int*)d_in[3];
    const float* eps    = (const float*)d_in[4];
    const float* W_ih   = (const float*)d_in[5];
    const float* W_hh   = (const float*)d_in[6];
    const float* b_ih   = (const float*)d_in[7];
    const float* b_hh   = (const float*)d_in[8];
    const float* W_z0   = (const float*)d_in[9];
    const float* b_z0   = (const float*)d_in[10];
    const float* oW1    = (const float*)d_in[11];
    const float* ob1    = (const float*)d_in[12];
    const float* oW2    = (const float*)d_in[13];
    const float* ob2    = (const float*)d_in[14];
    const float* oW3    = (const float*)d_in[15];
    const float* ob3    = (const float*)d_in[16];
    const float* dW1    = (const float*)d_in[17];
    const float* db1    = (const float*)d_in[18];
    const float* dW2    = (const float*)d_in[19];
    const float* db2    = (const float*)d_in[20];
    float* out = (float*)d_out;

    size_t gru_smem = (size_t)(2 * HDIM * G3 + 2 * 1024 + 2 * 1024 + 2 * G3) * sizeof(float);
    cudaFuncSetAttribute((const void*)gru_kernel,
                         cudaFuncAttributeMaxDynamicSharedMemorySize, (int)gru_smem);
    size_t ode_smem = (size_t)(2048 + 4096 + 2048 + 4 * 512 + 2 * 1024 + 160) * sizeof(float);
    cudaFuncSetAttribute((const void*)ode_kernel,
                         cudaFuncAttributeMaxDynamicSharedMemorySize, (int)ode_smem);

    gru_kernel<<<BATCH / 16, 256, gru_smem>>>(values, mask, seqlen, W_ih, W_hh, b_ih, b_hh);
    z0_kernel<<<(BATCH * LDIM) / 256, 256>>>(eps, W_z0, b_z0);
    ode_kernel<<<BATCH / 16, 256, ode_smem>>>(oW1, ob1, oW2, ob2, oW3, ob3,
                                              dW1, db1, dW2, db2, out);
    kl_kernel<<<1, 256>>>(out, out_size);
}

// round 5
// speedup vs baseline: 3.2182x; 1.1065x over previous
#include <cuda_runtime.h>

#define BATCH 2048
#define TT    256
#define NVAL  32
#define HDIM  64
#define G3    192
#define LDIM  32
#define OHDIM 64
#define ODE_STEPS 12

typedef unsigned long long u64;

// ---------------- persistent scratch ----------------
__device__ float g_h[BATCH * HDIM];
__device__ float g_z[BATCH * LDIM];
__device__ float g_klpart[256];

// ---------------- f32x2 packed-FMA helpers (sm_100a) ----------------
__device__ __forceinline__ u64 ffma2(u64 a, u64 b, u64 c) {
    u64 d;
    asm("fma.rn.f32x2 %0, %1, %2, %3;" : "=l"(d) : "l"(a), "l"(b), "l"(c));
    return d;
}
__device__ __forceinline__ float fsum2(u64 v) {
    float lo, hi;
    asm("mov.b64 {%0, %1}, %2;" : "=f"(lo), "=f"(hi) : "l"(v));
    return lo + hi;
}

// ---------------- fast transcendentals ----------------
__device__ __forceinline__ float fsig(float x) {
    x = fminf(fmaxf(x, -30.f), 30.f);
    return __fdividef(1.f, 1.f + __expf(-x));
}
__device__ __forceinline__ float ftanh(float x) {
    x = fminf(fmaxf(x, -15.f), 15.f);
    float e = __expf(2.f * x);
    return __fdividef(e - 1.f, e + 1.f);
}

// =====================================================================
// Kernel 1: fused input-projection + GRU scan.
// 16 rows/block, 512 threads (2 rows/thread) for latency hiding.
// Weights pre-packed as f32x2 pairs: Wp[kk][192][2] -> one LDS.64 per
// (gate,k-pair) access, conflict-free (lane stride 8B).
// =====================================================================
__global__ __launch_bounds__(512) void gru_kernel(
    const float* __restrict__ values, const float* __restrict__ mask,
    const int* __restrict__ seqlen,
    const float* __restrict__ W_ih, const float* __restrict__ W_hh,
    const float* __restrict__ b_ih, const float* __restrict__ b_hh)
{
    extern __shared__ float sm[];
    float* Wip = sm;                   // [32][192][2]
    float* Whp = Wip + 32 * 384;       // [32][192][2]
    float* xs  = Whp + 32 * 384;       // [2][16][64]
    float* hs  = xs + 2048;            // [2][16][64]
    float* bi  = hs + 2048;            // [192]
    float* bh  = bi + G3;              // [192]
    __shared__ int seq_s[16];

    const int tid = threadIdx.x;
    const int b0  = blockIdx.x * 16;

    // pre-pack weights: Wp[(k>>1)*384 + 2*g + (k&1)] = W[g][k]
    for (int i = tid; i < G3 * HDIM; i += 512) {
        int g = i >> 6, k = i & 63;
        int d = (k >> 1) * 384 + 2 * g + (k & 1);
        Wip[d] = W_ih[i];
        Whp[d] = W_hh[i];
    }
    for (int i = tid; i < G3; i += 512) { bi[i] = b_ih[i]; bh[i] = b_hh[i]; }
    for (int i = tid; i < 2048; i += 512) hs[i] = 0.f;
    if (tid < 16) seq_s[tid] = seqlen[b0 + tid];

    // stage x for t=0 (tr = TT-1)
    for (int i = tid; i < 1024; i += 512) {
        int r = i >> 6, k = i & 63;
        int base = ((b0 + r) * TT + (TT - 1)) * NVAL;
        xs[i] = (k < NVAL) ? values[base + k] : mask[base + k - NVAL];
    }
    __syncthreads();

    int tmax = 0;
    #pragma unroll
    for (int r = 0; r < 16; r++) tmax = max(tmax, seq_s[r]);

    const int j  = tid & 63;
    const int rg = tid >> 6;   // 8 groups of 2 rows

    for (int t = 0; t < tmax; t++) {
        const int cur = t & 1;
        const float* xcur = xs + cur * 1024;
        const float* hcur = hs + cur * 1024;
        float*       hnxt = hs + (cur ^ 1) * 1024;
        float*       xnxt = xs + (cur ^ 1) * 1024;

        // prefetch next timestep's x into registers
        float pf[2];
        const bool do_pf = (t + 1 < tmax);
        if (do_pf) {
            const int tr2 = TT - 2 - t;
            #pragma unroll
            for (int q = 0; q < 2; q++) {
                int i = tid + q * 512;
                int r = i >> 6, k = i & 63;
                int base = ((b0 + r) * TT + tr2) * NVAL;
                pf[q] = (k < NVAL) ? values[base + k] : mask[base + k - NVAL];
            }
        }

        u64 aR[2], aZ[2], aN[2], aH[2];
        #pragma unroll
        for (int rr = 0; rr < 2; rr++) { aR[rr] = 0; aZ[rr] = 0; aN[rr] = 0; aH[rr] = 0; }

        const float* wbase = Wip + 2 * j;
        const float* vbase = Whp + 2 * j;
        #pragma unroll 8
        for (int kk = 0; kk < 32; kk++) {
            u64 w0 = *(const u64*)&wbase[kk * 384];
            u64 w1 = *(const u64*)&wbase[kk * 384 + 128];
            u64 w2 = *(const u64*)&wbase[kk * 384 + 256];
            u64 v0 = *(const u64*)&vbase[kk * 384];
            u64 v1 = *(const u64*)&vbase[kk * 384 + 128];
            u64 v2 = *(const u64*)&vbase[kk * 384 + 256];
            #pragma unroll
            for (int rr = 0; rr < 2; rr++) {
                const int r = rg * 2 + rr;
                u64 xv = *(const u64*)&xcur[r * 64 + 2 * kk];   // LDS.64 broadcast
                u64 hv = *(const u64*)&hcur[r * 64 + 2 * kk];
                aR[rr] = ffma2(xv, w0, ffma2(hv, v0, aR[rr]));
                aZ[rr] = ffma2(xv, w1, ffma2(hv, v1, aZ[rr]));
                aN[rr] = ffma2(xv, w2, aN[rr]);
                aH[rr] = ffma2(hv, v2, aH[rr]);
            }
        }

        const float biR = bi[j] + bh[j];
        const float biZ = bi[j + 64] + bh[j + 64];
        const float biN = bi[j + 128];
        const float bhN = bh[j + 128];
        #pragma unroll
        for (int rr = 0; rr < 2; rr++) {
            const int r = rg * 2 + rr;
            float hold  = hcur[r * 64 + j];
            float rgate = fsig(fsum2(aR[rr]) + biR);
            float zgate = fsig(fsum2(aZ[rr]) + biZ);
            float n     = ftanh(fsum2(aN[rr]) + biN + rgate * (fsum2(aH[rr]) + bhN));
            float hnew  = (1.f - zgate) * n + zgate * hold;
            hnxt[r * 64 + j] = (t < seq_s[r]) ? hnew : hold;
        }

        if (do_pf) {
            #pragma unroll
            for (int q = 0; q < 2; q++) xnxt[tid + q * 512] = pf[q];
        }
        __syncthreads();
    }

    const float* hf = hs + (tmax & 1) * 1024;
    for (int i = tid; i < 1024; i += 512) {
        int r = i >> 6, k = i & 63;
        g_h[(b0 + r) * HDIM + k] = hf[i];
    }
}

// =====================================================================
// Kernel 2: z0 sample + KL partials.
// =====================================================================
__global__ __launch_bounds__(256) void z0_kernel(
    const float* __restrict__ eps, const float* __restrict__ W_z0,
    const float* __restrict__ b_z0)
{
    __shared__ float Wz[64 * 64];
    __shared__ float bz[64];
    __shared__ float red[256];
    int tid = threadIdx.x;
    for (int i = tid; i < 64 * 64; i += 256) {
        int g = i >> 6, k = i & 63;
        Wz[k * 64 + g] = W_z0[i];
    }
    if (tid < 64) bz[tid] = b_z0[tid];
    __syncthreads();

    int idx = blockIdx.x * 256 + tid;
    int b = idx >> 5, l = idx & 31;
    float m  = bz[l];
    float lv = bz[l + 32];
    const float* hb = g_h + b * 64;
    #pragma unroll 8
    for (int k = 0; k < 64; k++) {
        float hv = hb[k];
        m  += hv * Wz[k * 64 + l];
        lv += hv * Wz[k * 64 + l + 32];
    }
    g_z[idx] = m + eps[idx] * __expf(0.5f * lv);
    float klv = 1.f + lv - m * m - __expf(lv);

    red[tid] = klv;
    __syncthreads();
    for (int s = 128; s > 0; s >>= 1) {
        if (tid < s) red[tid] += red[tid + s];
        __syncthreads();
    }
    if (tid == 0) g_klpart[blockIdx.x] = red[0];
}

// =====================================================================
// Kernel 3: RK4 latent-ODE + fused decoder + (block 0) KL reduce.
// 256 threads, 16 rows/block; weights pre-packed for LDS.64 pair loads.
// =====================================================================
__global__ __launch_bounds__(256) void ode_kernel(
    const float* __restrict__ W1, const float* __restrict__ b1,
    const float* __restrict__ W2, const float* __restrict__ b2,
    const float* __restrict__ W3, const float* __restrict__ b3,
    const float* __restrict__ dW1, const float* __restrict__ db1,
    const float* __restrict__ dW2, const float* __restrict__ db2,
    float* __restrict__ out, int out_size)
{
    extern __shared__ float sm[];
    float* W1p = sm;            // [16][64][2]  W1p[kk*128+2j+p] = W1[j][2kk+p]
    float* W2p = W1p + 2048;    // [32][64][2]
    float* W3p = W2p + 4096;    // [32][32][2]
    float* zs  = W3p + 2048;    // [16][32]
    float* zt  = zs + 512;
    float* acc = zt + 512;
    float* fs  = acc + 512;
    float* h1  = fs + 512;      // [16][64]
    float* h2  = h1 + 1024;     // [16][64]
    float* sb1 = h2 + 1024;     // [64]
    float* sb2 = sb1 + 64;      // [64]
    float* sb3 = sb2 + 64;      // [32]

    const int tid = threadIdx.x;
    const int j  = tid & 63;
    const int rg = tid >> 6;
    const int b0 = blockIdx.x * 16;

    for (int i = tid; i < 64 * 32; i += 256) {  // W1 (64,32)
        int jj = i >> 5, k = i & 31;
        W1p[(k >> 1) * 128 + 2 * jj + (k & 1)] = W1[i];
    }
    for (int i = tid; i < 64 * 64; i += 256) {  // W2 (64,64)
        int jj = i >> 6, k = i & 63;
        W2p[(k >> 1) * 128 + 2 * jj + (k & 1)] = W2[i];
    }
    for (int i = tid; i < 32 * 64; i += 256) {  // W3 (32,64)
        int jj = i >> 6, k = i & 63;
        W3p[(k >> 1) * 64 + 2 * jj + (k & 1)] = W3[i];
    }
    if (tid < 64) { sb1[tid] = b1[tid]; sb2[tid] = b2[tid]; }
    if (tid < 32) sb3[tid] = b3[tid];
    for (int i = tid; i < 512; i += 256) zs[i] = g_z[b0 * 32 + i];
    __syncthreads();

    const float hstep = 48.f / (float)ODE_STEPS;

    auto mlp_eval = [&](const float* src) {
        // L1: src[16][32] -> h1[16][64]
        {
            u64 a[4] = {0, 0, 0, 0};
            #pragma unroll
            for (int kk = 0; kk < 16; kk++) {
                u64 w = *(const u64*)&W1p[kk * 128 + 2 * j];
                #pragma unroll
                for (int rr = 0; rr < 4; rr++) {
                    u64 s2 = *(const u64*)&src[(rg * 4 + rr) * 32 + 2 * kk];
                    a[rr] = ffma2(s2, w, a[rr]);
                }
            }
            float bb = sb1[j];
            #pragma unroll
            for (int rr = 0; rr < 4; rr++)
                h1[(rg * 4 + rr) * 64 + j] = ftanh(fsum2(a[rr]) + bb);
        }
        __syncthreads();
        // L2: h1 -> h2
        {
            u64 a[4] = {0, 0, 0, 0};
            #pragma unroll 8
            for (int kk = 0; kk < 32; kk++) {
                u64 w = *(const u64*)&W2p[kk * 128 + 2 * j];
                #pragma unroll
                for (int rr = 0; rr < 4; rr++) {
                    u64 s2 = *(const u64*)&h1[(rg * 4 + rr) * 64 + 2 * kk];
                    a[rr] = ffma2(s2, w, a[rr]);
                }
            }
            float bb = sb2[j];
            #pragma unroll
            for (int rr = 0; rr < 4; rr++)
                h2[(rg * 4 + rr) * 64 + j] = ftanh(fsum2(a[rr]) + bb);
        }
        __syncthreads();
        // L3: h2 -> fs[16][32] (half the lanes)
        if (j < 32) {
            u64 a[4] = {0, 0, 0, 0};
            #pragma unroll 8
            for (int kk = 0; kk < 32; kk++) {
                u64 w = *(const u64*)&W3p[kk * 64 + 2 * j];
                #pragma unroll
                for (int rr = 0; rr < 4; rr++) {
                    u64 s2 = *(const u64*)&h2[(rg * 4 + rr) * 64 + 2 * kk];
                    a[rr] = ffma2(s2, w, a[rr]);
                }
            }
            float bb = sb3[j];
            #pragma unroll
            for (int rr = 0; rr < 4; rr++)
                fs[(rg * 4 + rr) * 32 + j] = fsum2(a[rr]) + bb;
        }
        __syncthreads();
    };

    const int i0 = 2 * tid;
    for (int s = 0; s < ODE_STEPS; s++) {
        mlp_eval(zs);
        #pragma unroll
        for (int q = 0; q < 2; q++) { int i = i0 + q; float fv = fs[i]; acc[i] = fv; zt[i] = zs[i] + 0.5f * hstep * fv; }
        __syncthreads();
        mlp_eval(zt);
        #pragma unroll
        for (int q = 0; q < 2; q++) { int i = i0 + q; float fv = fs[i]; acc[i] += 2.f * fv; zt[i] = zs[i] + 0.5f * hstep * fv; }
        __syncthreads();
        mlp_eval(zt);
        #pragma unroll
        for (int q = 0; q < 2; q++) { int i = i0 + q; float fv = fs[i]; acc[i] += 2.f * fv; zt[i] = zs[i] + hstep * fv; }
        __syncthreads();
        mlp_eval(zt);
        #pragma unroll
        for (int q = 0; q < 2; q++) { int i = i0 + q; zs[i] += (hstep / 6.f) * (acc[i] + fs[i]); }
        __syncthreads();
    }

    // ---------- fused decoder: logits for this block's 16 rows ----------
    for (int i = tid; i < 64 * 32; i += 256) h1[i] = dW1[i];
    if (tid < 64) { acc[tid] = db1[tid]; acc[64 + tid] = dW2[tid]; }
    __syncthreads();

    const int lane = tid & 31;
    const int wrp  = tid >> 5;
    #pragma unroll
    for (int rr = 0; rr < 4; rr++) {
        const int r = rg * 4 + rr;
        float s = acc[j];
        #pragma unroll 8
        for (int k = 0; k < 32; k++) s += zs[r * 32 + k] * h1[j * 32 + k];
        float v = fmaxf(s, 0.f) * acc[64 + j];
        #pragma unroll
        for (int off = 16; off > 0; off >>= 1) v += __shfl_down_sync(0xffffffffu, v, off);
        if (lane == 0) fs[wrp * 4 + rr] = v;
    }
    __syncthreads();
    if (tid < 16) {
        int g = tid >> 2, rr = tid & 3;
        out[b0 + tid] = db2[0] + fs[(2 * g) * 4 + rr] + fs[(2 * g + 1) * 4 + rr];
    }

    // ---------- block 0: KL final reduce (z0_kernel finished before launch) ----------
    if (blockIdx.x == 0) {
        float* red = h2;   // dead scratch
        red[tid] = g_klpart[tid];
        __syncthreads();
        for (int s = 128; s > 0; s >>= 1) {
            if (tid < s) red[tid] += red[tid + s];
            __syncthreads();
        }
        if (tid == 0) out[out_size - 1] = -0.5f * red[0] / (float)(BATCH * LDIM);
    }
}

// =====================================================================
extern "C" void kernel_launch(void* const* d_in, const int* in_sizes, int n_in,
                              void* d_out, int out_size)
{
    const float* values = (const float*)d_in[1];
    const float* mask   = (const float*)d_in[2];
    const int*   seqlen = (const int*)d_in[3];
    const float* eps    = (const float*)d_in[4];
    const float* W_ih   = (const float*)d_in[5];
    const float* W_hh   = (const float*)d_in[6];
    const float* b_ih   = (const float*)d_in[7];
    const float* b_hh   = (const float*)d_in[8];
    const float* W_z0   = (const float*)d_in[9];
    const float* b_z0   = (const float*)d_in[10];
    const float* oW1    = (const float*)d_in[11];
    const float* ob1    = (const float*)d_in[12];
    const float* oW2    = (const float*)d_in[13];
    const float* ob2    = (const float*)d_in[14];
    const float* oW3    = (const float*)d_in[15];
    const float* ob3    = (const float*)d_in[16];
    const float* dW1    = (const float*)d_in[17];
    const float* db1    = (const float*)d_in[18];
    const float* dW2    = (const float*)d_in[19];
    const float* db2    = (const float*)d_in[20];
    float* out = (float*)d_out;

    size_t gru_smem = (size_t)(2 * 32 * 384 + 2 * 1024 + 2 * 1024 + 2 * G3) * sizeof(float);
    cudaFuncSetAttribute((const void*)gru_kernel,
                         cudaFuncAttributeMaxDynamicSharedMemorySize, (int)gru_smem);
    size_t ode_smem = (size_t)(2048 + 4096 + 2048 + 4 * 512 + 2 * 1024 + 160) * sizeof(float);
    cudaFuncSetAttribute((const void*)ode_kernel,
                         cudaFuncAttributeMaxDynamicSharedMemorySize, (int)ode_smem);

    gru_kernel<<<BATCH / 16, 512, gru_smem>>>(values, mask, seqlen, W_ih, W_hh, b_ih, b_hh);
    z0_kernel<<<(BATCH * LDIM) / 256, 256>>>(eps, W_z0, b_z0);
    ode_kernel<<<BATCH / 16, 256, ode_smem>>>(oW1, ob1, oW2, ob2, oW3, ob3,
                                              dW1, db1, dW2, db2, out, out_size);
}